// round 7
// baseline (speedup 1.0000x reference)
#include <cuda_runtime.h>
#include <math.h>

#define TT 8192          // tokens = B*S
#define DD 1024          // model dim
#define EE 8             // experts
#define HH 2048          // hidden
#define NROWS (TT*2)     // top-2 routing rows

// ---------------- scratch (static device globals; no allocations) ----------
__device__ int   g_tok_e[NROWS];
__device__ float g_tok_w[NROWS];
__device__ int   g_counts[EE];
__device__ int   g_offsets[EE+1];
__device__ int   g_cnt2[EE];
__device__ int   g_row2tok[NROWS];
__device__ float g_roww[NROWS];
__device__ int   g_pos[NROWS];
__device__ float g_H[(size_t)NROWS * HH];   // gelu(x@W1+b1), expert-grouped rows
__device__ float g_Y[(size_t)NROWS * DD];   // h@W2+b2

// ---------------- helpers ---------------------------------------------------
__device__ __forceinline__ unsigned f2tf(float f){
    unsigned r; asm("cvt.rna.tf32.f32 %0, %1;" : "=r"(r) : "f"(f)); return r;
}

// gelu(tanh approx): 0.5*x*(1+tanh(z)) == x * sigmoid(2z), exact identity
__device__ __forceinline__ float gelu_f(float v){
    float z = 0.7978845608028654f * (v + 0.044715f * v * v * v);
    float u = __expf(-2.0f * z);
    return __fdividef(v, 1.0f + u);
}

__device__ __forceinline__ void mma8(float* c, const unsigned* a, const unsigned* b){
    asm volatile(
        "mma.sync.aligned.m16n8k8.row.col.f32.tf32.tf32.f32 "
        "{%0,%1,%2,%3}, {%4,%5,%6,%7}, {%8,%9}, {%0,%1,%2,%3};"
        : "+f"(c[0]), "+f"(c[1]), "+f"(c[2]), "+f"(c[3])
        : "r"(a[0]), "r"(a[1]), "r"(a[2]), "r"(a[3]), "r"(b[0]), "r"(b[1]));
}

// ---------------- kernel 0: zero per-launch state ---------------------------
__global__ void init_kernel(){
    if (threadIdx.x < EE) g_counts[threadIdx.x] = 0;
}

// ---------------- kernel 1: gating + top-2 routing --------------------------
// grid 128 blocks x 256 threads; each block handles 64 tokens (warp/token x8)
__global__ void gate_kernel(const float* __restrict__ x,
                            const float* __restrict__ Wg,
                            const float* __restrict__ bg){
    __shared__ float sWg[DD*EE];    // 32 KB
    __shared__ int scnt[EE];
    const int tid = threadIdx.x;
    if (tid < EE) scnt[tid] = 0;
    for (int i = tid; i < DD*EE/4; i += 256)
        ((float4*)sWg)[i] = ((const float4*)Wg)[i];
    __syncthreads();

    const int warp = tid >> 5, lane = tid & 31;
    for (int i = 0; i < 8; ++i){
        const int t = blockIdx.x * 64 + i * 8 + warp;
        float acc[EE];
        #pragma unroll
        for (int e = 0; e < EE; ++e) acc[e] = 0.f;
        const float* xr = x + (size_t)t * DD;
        for (int j = 0; j < DD/32; ++j){
            const int d = j * 32 + lane;
            const float xv = xr[d];
            const float4* w4 = (const float4*)(sWg + d * EE);
            float4 wa = w4[0], wb = w4[1];
            acc[0] += xv*wa.x; acc[1] += xv*wa.y; acc[2] += xv*wa.z; acc[3] += xv*wa.w;
            acc[4] += xv*wb.x; acc[5] += xv*wb.y; acc[6] += xv*wb.z; acc[7] += xv*wb.w;
        }
        #pragma unroll
        for (int off = 16; off; off >>= 1){
            #pragma unroll
            for (int e = 0; e < EE; ++e)
                acc[e] += __shfl_xor_sync(0xffffffffu, acc[e], off);
        }
        if (lane == 0){
            float l[EE];
            #pragma unroll
            for (int e = 0; e < EE; ++e) l[e] = acc[e] + bg[e];
            int e0 = 0; float l0 = l[0];
            #pragma unroll
            for (int e = 1; e < EE; ++e) if (l[e] > l0){ l0 = l[e]; e0 = e; }
            int e1 = -1; float l1 = -1e30f;
            #pragma unroll
            for (int e = 0; e < EE; ++e) if (e != e0 && l[e] > l1){ l1 = l[e]; e1 = e; }
            // normalized top-2 softmax weights == sigmoid of logit gap (exact)
            const float w0 = 1.0f / (1.0f + __expf(l1 - l0));
            g_tok_e[2*t] = e0;  g_tok_e[2*t+1] = e1;
            g_tok_w[2*t] = w0;  g_tok_w[2*t+1] = 1.0f - w0;
            atomicAdd(&scnt[e0], 1); atomicAdd(&scnt[e1], 1);
        }
    }
    __syncthreads();
    if (tid < EE) atomicAdd(&g_counts[tid], scnt[tid]);
}

// ---------------- kernel 2: exclusive scan of counts ------------------------
__global__ void scan_kernel(){
    if (threadIdx.x == 0){
        int o = 0;
        #pragma unroll
        for (int e = 0; e < EE; ++e){ g_offsets[e] = o; o += g_counts[e]; }
        g_offsets[EE] = o;
    }
    if (threadIdx.x < EE) g_cnt2[threadIdx.x] = 0;
}

// ---------------- kernel 3: scatter tokens into expert-grouped rows ---------
__global__ void scatter_kernel(){
    __shared__ int sc[EE], sbase[EE];
    const int tid = threadIdx.x;
    if (tid < EE) sc[tid] = 0;
    __syncthreads();
    const int t = blockIdx.x * 256 + tid;
    const int e0 = g_tok_e[2*t], e1 = g_tok_e[2*t+1];
    const int s0 = atomicAdd(&sc[e0], 1);
    const int s1 = atomicAdd(&sc[e1], 1);
    __syncthreads();
    if (tid < EE) sbase[tid] = atomicAdd(&g_cnt2[tid], sc[tid]);
    __syncthreads();
    const int r0 = g_offsets[e0] + sbase[e0] + s0;
    const int r1 = g_offsets[e1] + sbase[e1] + s1;
    g_row2tok[r0] = t; g_roww[r0] = g_tok_w[2*t];   g_pos[2*t]   = r0;
    g_row2tok[r1] = t; g_roww[r1] = g_tok_w[2*t+1]; g_pos[2*t+1] = r1;
}

// ---------------- TF32 tensor-core grouped GEMM ------------------------------
// FIRST=true : C(g_H) = gelu( gather(x) @ W1[e] + b1[e] ),  KD=1024, ND=2048
// FIRST=false: C(g_Y) =        g_H       @ W2[e] + b2[e],   KD=2048, ND=1024
// Tiles: 128x128x32, 8 warps (4x2), warp tile 32x64 via m16n8k8 atoms.
template<int KD, int ND, bool FIRST>
__global__ __launch_bounds__(256, 2)
void gemm_kernel(const float* __restrict__ Ain,
                 const float* __restrict__ Wall,
                 const float* __restrict__ bias){
    constexpr int BM = 128, BN = 128, BK = 32;
    __shared__ float As[BM][BK + 4];   // +4 pad: frag loads conflict-free
    __shared__ float Bs[BK][BN + 8];   // +8 pad: frag loads conflict-free
    __shared__ int srow[BM];

    const int e    = blockIdx.y >> 6;           // 64 row-tiles per expert
    const int m0   = (blockIdx.y & 63) * BM;
    const int base = g_offsets[e];
    const int cnt  = g_offsets[e+1] - base;
    if (m0 >= cnt) return;                       // empty tile
    const int n0  = blockIdx.x * BN;
    const int tid = threadIdx.x;

    const float* Asrc = FIRST ? Ain : (const float*)g_H;
    float*       Cdst = FIRST ? (float*)g_H : (float*)g_Y;

    if (tid < BM){
        const int ok = (m0 + tid) < cnt;
        if (FIRST) srow[tid] = ok ? g_row2tok[base + m0 + tid] : 0;
        else       srow[tid] = ok ? (base + m0 + tid) : base;
    }
    __syncthreads();

    float c[2][8][4];
    #pragma unroll
    for (int i = 0; i < 2; ++i)
        #pragma unroll
        for (int j = 0; j < 8; ++j)
            #pragma unroll
            for (int q = 0; q < 4; ++q) c[i][j][q] = 0.f;

    const float* Wp = Wall + (size_t)e * KD * ND + n0;
    const int lane = tid & 31, wid = tid >> 5;
    const int wm = wid >> 1, wn = wid & 1;
    const int g = lane >> 2, tg = lane & 3;

    for (int kt = 0; kt < KD / BK; ++kt){
        // ---- load A tile (gathered rows), round to tf32 ----
        #pragma unroll
        for (int it = 0; it < 4; ++it){
            const int s = tid + it * 256;
            const int m = s >> 3, seg = s & 7;
            const float4 v = *(const float4*)(Asrc + (size_t)srow[m] * KD + kt * BK + seg * 4);
            As[m][seg*4+0] = __uint_as_float(f2tf(v.x));
            As[m][seg*4+1] = __uint_as_float(f2tf(v.y));
            As[m][seg*4+2] = __uint_as_float(f2tf(v.z));
            As[m][seg*4+3] = __uint_as_float(f2tf(v.w));
        }
        // ---- load B tile ----
        #pragma unroll
        for (int it = 0; it < 4; ++it){
            const int s = tid + it * 256;
            const int k = s >> 5, seg = s & 31;
            const float4 v = *(const float4*)(Wp + (size_t)(kt * BK + k) * ND + seg * 4);
            Bs[k][seg*4+0] = __uint_as_float(f2tf(v.x));
            Bs[k][seg*4+1] = __uint_as_float(f2tf(v.y));
            Bs[k][seg*4+2] = __uint_as_float(f2tf(v.z));
            Bs[k][seg*4+3] = __uint_as_float(f2tf(v.w));
        }
        __syncthreads();

        #pragma unroll
        for (int kk = 0; kk < BK; kk += 8){
            unsigned a[2][4];
            #pragma unroll
            for (int am = 0; am < 2; ++am){
                const int r = wm * 32 + am * 16 + g;
                a[am][0] = __float_as_uint(As[r    ][kk + tg    ]);
                a[am][1] = __float_as_uint(As[r + 8][kk + tg    ]);
                a[am][2] = __float_as_uint(As[r    ][kk + tg + 4]);
                a[am][3] = __float_as_uint(As[r + 8][kk + tg + 4]);
            }
            unsigned b[8][2];
            #pragma unroll
            for (int bn = 0; bn < 8; ++bn){
                const int ccol = wn * 64 + bn * 8 + g;
                b[bn][0] = __float_as_uint(Bs[kk + tg    ][ccol]);
                b[bn][1] = __float_as_uint(Bs[kk + tg + 4][ccol]);
            }
            #pragma unroll
            for (int am = 0; am < 2; ++am)
                #pragma unroll
                for (int bn = 0; bn < 8; ++bn)
                    mma8(c[am][bn], a[am], b[bn]);
        }
        __syncthreads();
    }

    // ---- epilogue: +bias [, gelu], store ----
    #pragma unroll
    for (int am = 0; am < 2; ++am){
        #pragma unroll
        for (int bn = 0; bn < 8; ++bn){
            const int ncol = n0 + wn * 64 + bn * 8 + 2 * tg;
            const float bb0 = bias[e * ND + ncol];
            const float bb1 = bias[e * ND + ncol + 1];
            #pragma unroll
            for (int half = 0; half < 2; ++half){
                const int r = wm * 32 + am * 16 + g + half * 8;
                if (m0 + r < cnt){
                    float v0 = c[am][bn][half*2+0] + bb0;
                    float v1 = c[am][bn][half*2+1] + bb1;
                    if (FIRST){ v0 = gelu_f(v0); v1 = gelu_f(v1); }
                    *(float2*)(Cdst + (size_t)(base + m0 + r) * ND + ncol) = make_float2(v0, v1);
                }
            }
        }
    }
}

// ---------------- kernel 6: weighted combine (no atomics) -------------------
__global__ void combine_kernel(float* __restrict__ out){
    const int t = blockIdx.x, i = threadIdx.x;
    const int r0 = g_pos[2*t], r1 = g_pos[2*t+1];
    const float w0 = g_roww[r0], w1 = g_roww[r1];
    const float4 a = ((const float4*)(g_Y + (size_t)r0 * DD))[i];
    const float4 b = ((const float4*)(g_Y + (size_t)r1 * DD))[i];
    float4 r;
    r.x = w0*a.x + w1*b.x; r.y = w0*a.y + w1*b.y;
    r.z = w0*a.z + w1*b.z; r.w = w0*a.w + w1*b.w;
    ((float4*)(out + (size_t)t * DD))[i] = r;
}

// ---------------- launch -----------------------------------------------------
extern "C" void kernel_launch(void* const* d_in, const int* in_sizes, int n_in,
                              void* d_out, int out_size){
    // input order: x, top_k(scalar int), Wg, bg, W1, b1, W2, b2
    // be robust to the scalar top_k being dropped from the input list
    const int sh = (n_in >= 8) ? 0 : -1;
    const float* x  = (const float*)d_in[0];
    const float* Wg = (const float*)d_in[2 + sh];
    const float* bg = (const float*)d_in[3 + sh];
    const float* W1 = (const float*)d_in[4 + sh];
    const float* b1 = (const float*)d_in[5 + sh];
    const float* W2 = (const float*)d_in[6 + sh];
    const float* b2 = (const float*)d_in[7 + sh];
    float* out = (float*)d_out;

    init_kernel<<<1, 32>>>();
    gate_kernel<<<128, 256>>>(x, Wg, bg);
    scan_kernel<<<1, 32>>>();
    scatter_kernel<<<TT/256, 256>>>();
    gemm_kernel<DD, HH, true ><<<dim3(HH/128, EE*64), 256>>>(x,       W1, b1);
    gemm_kernel<HH, DD, false><<<dim3(DD/128, EE*64), 256>>>(nullptr, W2, b2);
    combine_kernel<<<TT, 256>>>(out);
}

// round 8
// speedup vs baseline: 1.7653x; 1.7653x over previous
#include <cuda_runtime.h>
#include <math.h>

#define TT 8192          // tokens = B*S
#define DD 1024          // model dim
#define EE 8             // experts
#define HH 2048          // hidden
#define NROWS (TT*2)     // top-2 routing rows
#define PADROWS (NROWS + EE*128)     // expert-padded rows (17408)
#define MAXTILES (PADROWS/128)       // 136

// GEMM tile geometry (shared by both GEMMs)
#define BM 128
#define BN 256
#define BK 32
#define APAD 4           // A tile row stride = 36 floats (conflict-free frags)
#define BPAD 8           // B tile row stride = 264 floats
#define AFL (BM*(BK+APAD))           // 4608 floats / 18432 B
#define BFL (BK*(BN+BPAD))           // 8448 floats / 33792 B
#define STG_FL (AFL+BFL)             // 13056 floats
#define STG_BYTES (STG_FL*4)         // 52224 B
#define NSTAGE 3
#define SMEM_BYTES (NSTAGE*STG_BYTES + NSTAGE*8)

// ---------------- scratch (static device globals; no allocations) ----------
__device__ int   g_tok_e[NROWS];
__device__ float g_tok_w[NROWS];
__device__ int   g_counts[EE];
__device__ int   g_off_p[EE+1];           // 128-aligned expert offsets
__device__ int   g_cnt2[EE];
__device__ int   g_row2tok[PADROWS];
__device__ float g_roww[PADROWS];
__device__ int   g_pos[NROWS];
// pre-tiled operands: A tiles are [tile][ktile][128 x (32+4)] fp32(tf32 bits)
__device__ float g_Xg[(size_t)MAXTILES * (DD/BK) * AFL];   // ~80 MB
__device__ float g_H [(size_t)MAXTILES * (HH/BK) * AFL];   // ~160 MB
// B tiles: [e][kt][nt][32 x (256+8)]
__device__ float g_W1c[(size_t)EE * (DD/BK) * (HH/BN) * BFL];  // ~69 MB
__device__ float g_W2c[(size_t)EE * (HH/BK) * (DD/BN) * BFL];  // ~69 MB
__device__ float g_Y[(size_t)PADROWS * DD];                    // ~71 MB

// ---------------- helpers ---------------------------------------------------
__device__ __forceinline__ unsigned f2tf(float f){
    unsigned r; asm("cvt.rna.tf32.f32 %0, %1;" : "=r"(r) : "f"(f)); return r;
}
__device__ __forceinline__ float gelu_f(float v){
    float z = 0.7978845608028654f * (v + 0.044715f * v * v * v);
    float u = __expf(-2.0f * z);
    return __fdividef(v, 1.0f + u);
}
__device__ __forceinline__ void mma8(float* c, const unsigned* a, const unsigned* b){
    asm volatile(
        "mma.sync.aligned.m16n8k8.row.col.f32.tf32.tf32.f32 "
        "{%0,%1,%2,%3}, {%4,%5,%6,%7}, {%8,%9}, {%0,%1,%2,%3};"
        : "+f"(c[0]), "+f"(c[1]), "+f"(c[2]), "+f"(c[3])
        : "r"(a[0]), "r"(a[1]), "r"(a[2]), "r"(a[3]), "r"(b[0]), "r"(b[1]));
}
__device__ __forceinline__ unsigned s2u(const void* p){
    unsigned a;
    asm("{ .reg .u64 t; cvta.to.shared.u64 t, %1; cvt.u32.u64 %0, t; }" : "=r"(a) : "l"(p));
    return a;
}
__device__ __forceinline__ void mbar_init(unsigned mbar, unsigned cnt){
    asm volatile("mbarrier.init.shared.b64 [%0], %1;" :: "r"(mbar), "r"(cnt) : "memory");
}
__device__ __forceinline__ void mbar_expect(unsigned mbar, unsigned bytes){
    asm volatile("mbarrier.arrive.expect_tx.shared.b64 _, [%0], %1;" :: "r"(mbar), "r"(bytes) : "memory");
}
__device__ __forceinline__ void mbar_wait(unsigned mbar, unsigned parity){
    asm volatile(
        "{\n\t"
        ".reg .pred P;\n\t"
        "LAB_%=:\n\t"
        "mbarrier.try_wait.parity.acquire.cta.shared::cta.b64 P, [%0], %1, 0x989680;\n\t"
        "@!P bra LAB_%=;\n\t"
        "}"
        :: "r"(mbar), "r"(parity) : "memory");
}
__device__ __forceinline__ void bulk_g2s(unsigned dst, const void* src, unsigned bytes, unsigned mbar){
    asm volatile(
        "cp.async.bulk.shared::cluster.global.mbarrier::complete_tx::bytes [%0], [%1], %2, [%3];"
        :: "r"(dst), "l"(src), "r"(bytes), "r"(mbar) : "memory");
}

// ---------------- kernel 0: zero per-launch state ---------------------------
__global__ void init_kernel(){
    if (threadIdx.x < EE) g_counts[threadIdx.x] = 0;
}

// ---------------- kernel 1: gating + top-2 routing --------------------------
__global__ void gate_kernel(const float* __restrict__ x,
                            const float* __restrict__ Wg,
                            const float* __restrict__ bg){
    __shared__ float sWg[DD*EE];
    __shared__ int scnt[EE];
    const int tid = threadIdx.x;
    if (tid < EE) scnt[tid] = 0;
    for (int i = tid; i < DD*EE/4; i += 256)
        ((float4*)sWg)[i] = ((const float4*)Wg)[i];
    __syncthreads();

    const int warp = tid >> 5, lane = tid & 31;
    for (int i = 0; i < 8; ++i){
        const int t = blockIdx.x * 64 + i * 8 + warp;
        float acc[EE];
        #pragma unroll
        for (int e = 0; e < EE; ++e) acc[e] = 0.f;
        const float* xr = x + (size_t)t * DD;
        for (int j = 0; j < DD/32; ++j){
            const int d = j * 32 + lane;
            const float xv = xr[d];
            const float4* w4 = (const float4*)(sWg + d * EE);
            float4 wa = w4[0], wb = w4[1];
            acc[0] += xv*wa.x; acc[1] += xv*wa.y; acc[2] += xv*wa.z; acc[3] += xv*wa.w;
            acc[4] += xv*wb.x; acc[5] += xv*wb.y; acc[6] += xv*wb.z; acc[7] += xv*wb.w;
        }
        #pragma unroll
        for (int off = 16; off; off >>= 1){
            #pragma unroll
            for (int e = 0; e < EE; ++e)
                acc[e] += __shfl_xor_sync(0xffffffffu, acc[e], off);
        }
        if (lane == 0){
            float l[EE];
            #pragma unroll
            for (int e = 0; e < EE; ++e) l[e] = acc[e] + bg[e];
            int e0 = 0; float l0 = l[0];
            #pragma unroll
            for (int e = 1; e < EE; ++e) if (l[e] > l0){ l0 = l[e]; e0 = e; }
            int e1 = -1; float l1 = -1e30f;
            #pragma unroll
            for (int e = 0; e < EE; ++e) if (e != e0 && l[e] > l1){ l1 = l[e]; e1 = e; }
            const float w0 = 1.0f / (1.0f + __expf(l1 - l0));
            g_tok_e[2*t] = e0;  g_tok_e[2*t+1] = e1;
            g_tok_w[2*t] = w0;  g_tok_w[2*t+1] = 1.0f - w0;
            atomicAdd(&scnt[e0], 1); atomicAdd(&scnt[e1], 1);
        }
    }
    __syncthreads();
    if (tid < EE) atomicAdd(&g_counts[tid], scnt[tid]);
}

// ---------------- kernel 2: padded exclusive scan ----------------------------
__global__ void scan_kernel(){
    if (threadIdx.x == 0){
        int o = 0;
        #pragma unroll
        for (int e = 0; e < EE; ++e){
            g_off_p[e] = o;
            o += ((g_counts[e] + 127) >> 7) << 7;
        }
        g_off_p[EE] = o;
    }
    if (threadIdx.x < EE) g_cnt2[threadIdx.x] = 0;
}

// ---------------- kernel 3: scatter tokens into expert-grouped rows ---------
__global__ void scatter_kernel(){
    __shared__ int sc[EE], sbase[EE];
    const int tid = threadIdx.x;
    if (tid < EE) sc[tid] = 0;
    __syncthreads();
    const int t = blockIdx.x * 256 + tid;
    const int e0 = g_tok_e[2*t], e1 = g_tok_e[2*t+1];
    const int s0 = atomicAdd(&sc[e0], 1);
    const int s1 = atomicAdd(&sc[e1], 1);
    __syncthreads();
    if (tid < EE) sbase[tid] = atomicAdd(&g_cnt2[tid], sc[tid]);
    __syncthreads();
    const int r0 = g_off_p[e0] + sbase[e0] + s0;
    const int r1 = g_off_p[e1] + sbase[e1] + s1;
    g_row2tok[r0] = t; g_roww[r0] = g_tok_w[2*t];   g_pos[2*t]   = r0;
    g_row2tok[r1] = t; g_roww[r1] = g_tok_w[2*t+1]; g_pos[2*t+1] = r1;
}

// ---------------- kernel 4: mark padding rows --------------------------------
__global__ void padfill_kernel(){
    const int e = blockIdx.x;
    const int cnt = g_counts[e];
    const int pcnt = ((cnt + 127) >> 7) << 7;
    for (int i = cnt + threadIdx.x; i < pcnt; i += 128)
        g_row2tok[g_off_p[e] + i] = -1;
}

// ---------------- kernel 5: gather x rows into tiled/padded tf32 A buffer ---
// one block per padded row; thread j handles one float4 of D
__global__ void gather_kernel(const float* __restrict__ x){
    const int pr = blockIdx.x;
    if (pr >= g_off_p[EE]) return;
    const int tok = g_row2tok[pr];
    const int tile = pr >> 7, rl = pr & 127;
    const int j = threadIdx.x;               // 0..255
    const int kt = j >> 3, kin = (j & 7) * 4;
    float4 v = make_float4(0.f, 0.f, 0.f, 0.f);
    if (tok >= 0) v = *(const float4*)(x + (size_t)tok * DD + kt * BK + kin);
    float4 o;
    o.x = __uint_as_float(f2tf(v.x)); o.y = __uint_as_float(f2tf(v.y));
    o.z = __uint_as_float(f2tf(v.z)); o.w = __uint_as_float(f2tf(v.w));
    *(float4*)(g_Xg + ((size_t)tile * (DD/BK) + kt) * AFL + rl * (BK+APAD) + kin) = o;
}

// ---------------- kernel 6: convert weights into tiled/padded tf32 B tiles --
template<int KT, int NT>
__global__ void convw_kernel(const float* __restrict__ W, float* __restrict__ dst){
    size_t i = (size_t)blockIdx.x * 256 + threadIdx.x;     // float4 index
    const int n4 = (int)(i & 63);
    size_t r = i >> 6;
    const int kk = (int)(r & 31); r >>= 5;
    const int nt = (int)(r % NT); r /= NT;
    const int kt = (int)(r % KT); r /= KT;
    const int e  = (int)r;
    const float4 v = *(const float4*)(W +
        (((size_t)e * KT + kt) * 32 + kk) * (size_t)(NT * 256) + nt * 256 + n4 * 4);
    float4 o;
    o.x = __uint_as_float(f2tf(v.x)); o.y = __uint_as_float(f2tf(v.y));
    o.z = __uint_as_float(f2tf(v.z)); o.w = __uint_as_float(f2tf(v.w));
    *(float4*)(dst + ((((size_t)e * KT + kt) * NT + nt) * 32 + kk) * (BN+BPAD) + n4 * 4) = o;
}

// ---------------- TF32 tensor-core grouped GEMM, bulk-copy pipelined --------
// FIRST=true : g_H tiles = tf32(gelu( g_Xg @ W1c + b1 )),  KT=32, NT=8
// FIRST=false: g_Y rows  =           g_H  @ W2c + b2,      KT=64, NT=4
template<int KT, int NT, bool FIRST>
__global__ __launch_bounds__(512, 1)
void gemm_kernel(const float* __restrict__ Bw, const float* __restrict__ bias){
    extern __shared__ float smf[];
    const int e   = blockIdx.y >> 6;
    const int mt  = blockIdx.y & 63;
    const int cnt = g_counts[e];
    if (mt * BM >= cnt) return;
    const int tile = (g_off_p[e] >> 7) + mt;
    const int nt   = blockIdx.x;
    const int tid  = threadIdx.x;

    const float* Asrc = FIRST ? g_Xg : g_H;
    const unsigned sb  = s2u(smf);
    const unsigned mb0 = sb + NSTAGE * STG_BYTES;

    if (tid == 0){
        #pragma unroll
        for (int s = 0; s < NSTAGE; ++s) mbar_init(mb0 + 8*s, 1);
    }
    __syncthreads();

    if (tid == 0){
        #pragma unroll
        for (int s = 0; s < NSTAGE; ++s){
            mbar_expect(mb0 + 8*s, STG_BYTES);
            bulk_g2s(sb + s*STG_BYTES,           Asrc + ((size_t)tile*KT + s)*AFL, AFL*4, mb0 + 8*s);
            bulk_g2s(sb + s*STG_BYTES + AFL*4,   Bw + (((size_t)e*KT + s)*NT + nt)*BFL, BFL*4, mb0 + 8*s);
        }
    }

    float c[2][8][4];
    #pragma unroll
    for (int i = 0; i < 2; ++i)
        #pragma unroll
        for (int j = 0; j < 8; ++j)
            #pragma unroll
            for (int q = 0; q < 4; ++q) c[i][j][q] = 0.f;

    const int lane = tid & 31, wid = tid >> 5;
    const int wm = wid >> 2, wn = wid & 3;       // 4x4 warp grid, warp tile 32x64
    const int g = lane >> 2, tg = lane & 3;

    int s = 0, ph = 0;
    for (int kt = 0; kt < KT; ++kt){
        mbar_wait(mb0 + 8*s, ph);
        const float* As = smf + s * STG_FL;
        const float* Bs = As + AFL;

        #pragma unroll
        for (int kk = 0; kk < BK; kk += 8){
            unsigned a[2][4];
            #pragma unroll
            for (int am = 0; am < 2; ++am){
                const int r = wm*32 + am*16 + g;
                a[am][0] = __float_as_uint(As[(r    )*(BK+APAD) + kk + tg    ]);
                a[am][1] = __float_as_uint(As[(r + 8)*(BK+APAD) + kk + tg    ]);
                a[am][2] = __float_as_uint(As[(r    )*(BK+APAD) + kk + tg + 4]);
                a[am][3] = __float_as_uint(As[(r + 8)*(BK+APAD) + kk + tg + 4]);
            }
            #pragma unroll
            for (int bn = 0; bn < 8; ++bn){
                unsigned b[2];
                const int cc = wn*64 + bn*8 + g;
                b[0] = __float_as_uint(Bs[(kk + tg    )*(BN+BPAD) + cc]);
                b[1] = __float_as_uint(Bs[(kk + tg + 4)*(BN+BPAD) + cc]);
                mma8(c[0][bn], a[0], b);
                mma8(c[1][bn], a[1], b);
            }
        }
        __syncthreads();
        if (tid == 0 && kt + NSTAGE < KT){
            mbar_expect(mb0 + 8*s, STG_BYTES);
            bulk_g2s(sb + s*STG_BYTES,         Asrc + ((size_t)tile*KT + kt + NSTAGE)*AFL, AFL*4, mb0 + 8*s);
            bulk_g2s(sb + s*STG_BYTES + AFL*4, Bw + (((size_t)e*KT + kt + NSTAGE)*NT + nt)*BFL, BFL*4, mb0 + 8*s);
        }
        if (++s == NSTAGE){ s = 0; ph ^= 1; }
    }

    // ---- epilogue ----
    #pragma unroll
    for (int am = 0; am < 2; ++am){
        #pragma unroll
        for (int bn = 0; bn < 8; ++bn){
            const int lc = wn*64 + bn*8 + 2*tg;
            const int gc = nt*BN + lc;                 // global output column
            const float bb0 = bias[e*(NT*BN) + gc];
            const float bb1 = bias[e*(NT*BN) + gc + 1];
            #pragma unroll
            for (int h = 0; h < 2; ++h){
                const int r = wm*32 + am*16 + g + h*8;
                float v0 = c[am][bn][h*2+0] + bb0;
                float v1 = c[am][bn][h*2+1] + bb1;
                if (FIRST){
                    v0 = __uint_as_float(f2tf(gelu_f(v0)));
                    v1 = __uint_as_float(f2tf(gelu_f(v1)));
                    float* dst = g_H + ((size_t)tile*(HH/BK) + (gc >> 5))*AFL
                               + r*(BK+APAD) + (gc & 31);
                    *(float2*)dst = make_float2(v0, v1);
                } else {
                    float* dst = g_Y + ((size_t)(tile*BM + r))*DD + gc;
                    *(float2*)dst = make_float2(v0, v1);
                }
            }
        }
    }
}

// ---------------- kernel 9: weighted combine (no atomics) -------------------
__global__ void combine_kernel(float* __restrict__ out){
    const int t = blockIdx.x, i = threadIdx.x;
    const int r0 = g_pos[2*t], r1 = g_pos[2*t+1];
    const float w0 = g_roww[r0], w1 = g_roww[r1];
    const float4 a = ((const float4*)(g_Y + (size_t)r0 * DD))[i];
    const float4 b = ((const float4*)(g_Y + (size_t)r1 * DD))[i];
    float4 r;
    r.x = w0*a.x + w1*b.x; r.y = w0*a.y + w1*b.y;
    r.z = w0*a.z + w1*b.z; r.w = w0*a.w + w1*b.w;
    ((float4*)(out + (size_t)t * DD))[i] = r;
}

// ---------------- launch -----------------------------------------------------
extern "C" void kernel_launch(void* const* d_in, const int* in_sizes, int n_in,
                              void* d_out, int out_size){
    // input order: x, top_k(scalar), Wg, bg, W1, b1, W2, b2 (robust to dropped scalar)
    const int sh = (n_in >= 8) ? 0 : -1;
    const float* x  = (const float*)d_in[0];
    const float* Wg = (const float*)d_in[2 + sh];
    const float* bg = (const float*)d_in[3 + sh];
    const float* W1 = (const float*)d_in[4 + sh];
    const float* b1 = (const float*)d_in[5 + sh];
    const float* W2 = (const float*)d_in[6 + sh];
    const float* b2 = (const float*)d_in[7 + sh];
    float* out = (float*)d_out;

    float* w1c; cudaGetSymbolAddress((void**)&w1c, g_W1c);
    float* w2c; cudaGetSymbolAddress((void**)&w2c, g_W2c);

    // opt into >48KB dynamic smem (host-side attribute set; not a stream op)
    cudaFuncSetAttribute(gemm_kernel<DD/BK, HH/BN, true >,
                         cudaFuncAttributeMaxDynamicSharedMemorySize, SMEM_BYTES);
    cudaFuncSetAttribute(gemm_kernel<HH/BK, DD/BN, false>,
                         cudaFuncAttributeMaxDynamicSharedMemorySize, SMEM_BYTES);

    init_kernel<<<1, 32>>>();
    gate_kernel<<<128, 256>>>(x, Wg, bg);
    scan_kernel<<<1, 32>>>();
    scatter_kernel<<<TT/256, 256>>>();
    padfill_kernel<<<EE, 128>>>();
    gather_kernel<<<PADROWS, 256>>>(x);
    convw_kernel<DD/BK, HH/BN><<<16384, 256>>>(W1, w1c);
    convw_kernel<HH/BK, DD/BN><<<16384, 256>>>(W2, w2c);
    gemm_kernel<DD/BK, HH/BN, true ><<<dim3(HH/BN, EE*64), 512, SMEM_BYTES>>>(w1c, b1);
    gemm_kernel<HH/BK, DD/BN, false><<<dim3(DD/BN, EE*64), 512, SMEM_BYTES>>>(w2c, b2);
    combine_kernel<<<TT, 256>>>(out);
}

// round 9
// speedup vs baseline: 1.7663x; 1.0006x over previous
#include <cuda_runtime.h>
#include <math.h>

#define TT 8192          // tokens = B*S
#define DD 1024          // model dim
#define EE 8             // experts
#define HH 2048          // hidden
#define NROWS (TT*2)     // top-2 routing rows
#define PADROWS (NROWS + EE*128)     // expert-padded rows (17408)
#define MAXTILES (PADROWS/128)       // 136

// GEMM tile geometry (shared by both GEMMs)
#define BM 128
#define BN 256
#define BK 32
#define APAD 4           // A tile row stride = 36 floats (conflict-free frags)
#define BPAD 8           // B tile row stride = 264 floats
#define AFL (BM*(BK+APAD))           // 4608 floats / 18432 B
#define BFL (BK*(BN+BPAD))           // 8448 floats / 33792 B
#define STG_FL (AFL+BFL)             // 13056 floats
#define STG_BYTES (STG_FL*4)         // 52224 B
#define NSTAGE 3
#define SMEM_BYTES (NSTAGE*STG_BYTES + NSTAGE*8)

// ---------------- scratch (static device globals; no allocations) ----------
__device__ int   g_tok_e[NROWS];
__device__ float g_tok_w[NROWS];
__device__ int   g_counts[EE];
__device__ int   g_off_p[EE+1];           // 128-aligned expert offsets
__device__ int   g_cnt2[EE];
__device__ int   g_row2tok[PADROWS];
__device__ float g_roww[PADROWS];
__device__ int   g_pos[NROWS];
// pre-tiled operands: A tiles are [tile][ktile][128 x (32+4)] fp32(tf32 bits)
__device__ float g_Xg[(size_t)MAXTILES * (DD/BK) * AFL];   // ~80 MB
__device__ float g_H [(size_t)MAXTILES * (HH/BK) * AFL];   // ~160 MB
// B tiles: [e][kt][nt][32 x (256+8)]
__device__ float g_W1c[(size_t)EE * (DD/BK) * (HH/BN) * BFL];  // ~69 MB
__device__ float g_W2c[(size_t)EE * (HH/BK) * (DD/BN) * BFL];  // ~69 MB
__device__ float g_Y[(size_t)PADROWS * DD];                    // ~71 MB

// ---------------- helpers ---------------------------------------------------
__device__ __forceinline__ unsigned f2tf(float f){
    unsigned r; asm("cvt.rna.tf32.f32 %0, %1;" : "=r"(r) : "f"(f)); return r;
}
__device__ __forceinline__ float gelu_f(float v){
    float z = 0.7978845608028654f * (v + 0.044715f * v * v * v);
    float u = __expf(-2.0f * z);
    return __fdividef(v, 1.0f + u);
}
__device__ __forceinline__ void mma8(float* c, const unsigned* a, const unsigned* b){
    asm volatile(
        "mma.sync.aligned.m16n8k8.row.col.f32.tf32.tf32.f32 "
        "{%0,%1,%2,%3}, {%4,%5,%6,%7}, {%8,%9}, {%0,%1,%2,%3};"
        : "+f"(c[0]), "+f"(c[1]), "+f"(c[2]), "+f"(c[3])
        : "r"(a[0]), "r"(a[1]), "r"(a[2]), "r"(a[3]), "r"(b[0]), "r"(b[1]));
}
__device__ __forceinline__ unsigned s2u(const void* p){
    unsigned a;
    asm("{ .reg .u64 t; cvta.to.shared.u64 t, %1; cvt.u32.u64 %0, t; }" : "=r"(a) : "l"(p));
    return a;
}
__device__ __forceinline__ void mbar_init(unsigned mbar, unsigned cnt){
    asm volatile("mbarrier.init.shared.b64 [%0], %1;" :: "r"(mbar), "r"(cnt) : "memory");
}
__device__ __forceinline__ void mbar_expect(unsigned mbar, unsigned bytes){
    asm volatile("mbarrier.arrive.expect_tx.shared.b64 _, [%0], %1;" :: "r"(mbar), "r"(bytes) : "memory");
}
__device__ __forceinline__ void mbar_wait(unsigned mbar, unsigned parity){
    asm volatile(
        "{\n\t"
        ".reg .pred P;\n\t"
        "LAB_%=:\n\t"
        "mbarrier.try_wait.parity.acquire.cta.shared::cta.b64 P, [%0], %1, 0x989680;\n\t"
        "@!P bra LAB_%=;\n\t"
        "}"
        :: "r"(mbar), "r"(parity) : "memory");
}
__device__ __forceinline__ void bulk_g2s(unsigned dst, const void* src, unsigned bytes, unsigned mbar){
    asm volatile(
        "cp.async.bulk.shared::cluster.global.mbarrier::complete_tx::bytes [%0], [%1], %2, [%3];"
        :: "r"(dst), "l"(src), "r"(bytes), "r"(mbar) : "memory");
}

// ---------------- kernel 0: zero per-launch state ---------------------------
__global__ void init_kernel(){
    if (threadIdx.x < EE) g_counts[threadIdx.x] = 0;
}

// ---------------- kernel 1: gating + top-2 routing --------------------------
__global__ void gate_kernel(const float* __restrict__ x,
                            const float* __restrict__ Wg,
                            const float* __restrict__ bg){
    __shared__ float sWg[DD*EE];
    __shared__ int scnt[EE];
    const int tid = threadIdx.x;
    if (tid < EE) scnt[tid] = 0;
    for (int i = tid; i < DD*EE/4; i += 256)
        ((float4*)sWg)[i] = ((const float4*)Wg)[i];
    __syncthreads();

    const int warp = tid >> 5, lane = tid & 31;
    for (int i = 0; i < 8; ++i){
        const int t = blockIdx.x * 64 + i * 8 + warp;
        float acc[EE];
        #pragma unroll
        for (int e = 0; e < EE; ++e) acc[e] = 0.f;
        const float* xr = x + (size_t)t * DD;
        for (int j = 0; j < DD/32; ++j){
            const int d = j * 32 + lane;
            const float xv = xr[d];
            const float4* w4 = (const float4*)(sWg + d * EE);
            float4 wa = w4[0], wb = w4[1];
            acc[0] += xv*wa.x; acc[1] += xv*wa.y; acc[2] += xv*wa.z; acc[3] += xv*wa.w;
            acc[4] += xv*wb.x; acc[5] += xv*wb.y; acc[6] += xv*wb.z; acc[7] += xv*wb.w;
        }
        #pragma unroll
        for (int off = 16; off; off >>= 1){
            #pragma unroll
            for (int e = 0; e < EE; ++e)
                acc[e] += __shfl_xor_sync(0xffffffffu, acc[e], off);
        }
        if (lane == 0){
            float l[EE];
            #pragma unroll
            for (int e = 0; e < EE; ++e) l[e] = acc[e] + bg[e];
            int e0 = 0; float l0 = l[0];
            #pragma unroll
            for (int e = 1; e < EE; ++e) if (l[e] > l0){ l0 = l[e]; e0 = e; }
            int e1 = -1; float l1 = -1e30f;
            #pragma unroll
            for (int e = 0; e < EE; ++e) if (e != e0 && l[e] > l1){ l1 = l[e]; e1 = e; }
            const float w0 = 1.0f / (1.0f + __expf(l1 - l0));
            g_tok_e[2*t] = e0;  g_tok_e[2*t+1] = e1;
            g_tok_w[2*t] = w0;  g_tok_w[2*t+1] = 1.0f - w0;
            atomicAdd(&scnt[e0], 1); atomicAdd(&scnt[e1], 1);
        }
    }
    __syncthreads();
    if (tid < EE) atomicAdd(&g_counts[tid], scnt[tid]);
}

// ---------------- kernel 2: padded exclusive scan ----------------------------
__global__ void scan_kernel(){
    if (threadIdx.x == 0){
        int o = 0;
        #pragma unroll
        for (int e = 0; e < EE; ++e){
            g_off_p[e] = o;
            o += ((g_counts[e] + 127) >> 7) << 7;
        }
        g_off_p[EE] = o;
    }
    if (threadIdx.x < EE) g_cnt2[threadIdx.x] = 0;
}

// ---------------- kernel 3: scatter tokens into expert-grouped rows ---------
__global__ void scatter_kernel(){
    __shared__ int sc[EE], sbase[EE];
    const int tid = threadIdx.x;
    if (tid < EE) sc[tid] = 0;
    __syncthreads();
    const int t = blockIdx.x * 256 + tid;
    const int e0 = g_tok_e[2*t], e1 = g_tok_e[2*t+1];
    const int s0 = atomicAdd(&sc[e0], 1);
    const int s1 = atomicAdd(&sc[e1], 1);
    __syncthreads();
    if (tid < EE) sbase[tid] = atomicAdd(&g_cnt2[tid], sc[tid]);
    __syncthreads();
    const int r0 = g_off_p[e0] + sbase[e0] + s0;
    const int r1 = g_off_p[e1] + sbase[e1] + s1;
    g_row2tok[r0] = t; g_roww[r0] = g_tok_w[2*t];   g_pos[2*t]   = r0;
    g_row2tok[r1] = t; g_roww[r1] = g_tok_w[2*t+1]; g_pos[2*t+1] = r1;
}

// ---------------- kernel 4: mark padding rows --------------------------------
__global__ void padfill_kernel(){
    const int e = blockIdx.x;
    const int cnt = g_counts[e];
    const int pcnt = ((cnt + 127) >> 7) << 7;
    for (int i = cnt + threadIdx.x; i < pcnt; i += 128)
        g_row2tok[g_off_p[e] + i] = -1;
}

// ---------------- kernel 5: gather x rows into tiled/padded tf32 A buffer ---
// one block per padded row; thread j handles one float4 of D
__global__ void gather_kernel(const float* __restrict__ x){
    const int pr = blockIdx.x;
    if (pr >= g_off_p[EE]) return;
    const int tok = g_row2tok[pr];
    const int tile = pr >> 7, rl = pr & 127;
    const int j = threadIdx.x;               // 0..255
    const int kt = j >> 3, kin = (j & 7) * 4;
    float4 v = make_float4(0.f, 0.f, 0.f, 0.f);
    if (tok >= 0) v = *(const float4*)(x + (size_t)tok * DD + kt * BK + kin);
    float4 o;
    o.x = __uint_as_float(f2tf(v.x)); o.y = __uint_as_float(f2tf(v.y));
    o.z = __uint_as_float(f2tf(v.z)); o.w = __uint_as_float(f2tf(v.w));
    *(float4*)(g_Xg + ((size_t)tile * (DD/BK) + kt) * AFL + rl * (BK+APAD) + kin) = o;
}

// ---------------- kernel 6: convert weights into tiled/padded tf32 B tiles --
template<int KT, int NT>
__global__ void convw_kernel(const float* __restrict__ W, float* __restrict__ dst){
    size_t i = (size_t)blockIdx.x * 256 + threadIdx.x;     // float4 index
    const int n4 = (int)(i & 63);
    size_t r = i >> 6;
    const int kk = (int)(r & 31); r >>= 5;
    const int nt = (int)(r % NT); r /= NT;
    const int kt = (int)(r % KT); r /= KT;
    const int e  = (int)r;
    const float4 v = *(const float4*)(W +
        (((size_t)e * KT + kt) * 32 + kk) * (size_t)(NT * 256) + nt * 256 + n4 * 4);
    float4 o;
    o.x = __uint_as_float(f2tf(v.x)); o.y = __uint_as_float(f2tf(v.y));
    o.z = __uint_as_float(f2tf(v.z)); o.w = __uint_as_float(f2tf(v.w));
    *(float4*)(dst + ((((size_t)e * KT + kt) * NT + nt) * 32 + kk) * (BN+BPAD) + n4 * 4) = o;
}

// ---------------- TF32 tensor-core grouped GEMM, bulk-copy pipelined --------
// FIRST=true : g_H tiles = tf32(gelu( g_Xg @ W1c + b1 )),  KT=32, NT=8
// FIRST=false: g_Y rows  =           g_H  @ W2c + b2,      KT=64, NT=4
template<int KT, int NT, bool FIRST>
__global__ __launch_bounds__(512, 1)
void gemm_kernel(const float* __restrict__ Bw, const float* __restrict__ bias){
    extern __shared__ float smf[];
    const int e   = blockIdx.y >> 6;
    const int mt  = blockIdx.y & 63;
    const int cnt = g_counts[e];
    if (mt * BM >= cnt) return;
    const int tile = (g_off_p[e] >> 7) + mt;
    const int nt   = blockIdx.x;
    const int tid  = threadIdx.x;

    const float* Asrc = FIRST ? g_Xg : g_H;
    const unsigned sb  = s2u(smf);
    const unsigned mb0 = sb + NSTAGE * STG_BYTES;

    if (tid == 0){
        #pragma unroll
        for (int s = 0; s < NSTAGE; ++s) mbar_init(mb0 + 8*s, 1);
    }
    __syncthreads();

    if (tid == 0){
        #pragma unroll
        for (int s = 0; s < NSTAGE; ++s){
            mbar_expect(mb0 + 8*s, STG_BYTES);
            bulk_g2s(sb + s*STG_BYTES,           Asrc + ((size_t)tile*KT + s)*AFL, AFL*4, mb0 + 8*s);
            bulk_g2s(sb + s*STG_BYTES + AFL*4,   Bw + (((size_t)e*KT + s)*NT + nt)*BFL, BFL*4, mb0 + 8*s);
        }
    }

    float c[2][8][4];
    #pragma unroll
    for (int i = 0; i < 2; ++i)
        #pragma unroll
        for (int j = 0; j < 8; ++j)
            #pragma unroll
            for (int q = 0; q < 4; ++q) c[i][j][q] = 0.f;

    const int lane = tid & 31, wid = tid >> 5;
    const int wm = wid >> 2, wn = wid & 3;       // 4x4 warp grid, warp tile 32x64
    const int g = lane >> 2, tg = lane & 3;

    int s = 0, ph = 0;
    for (int kt = 0; kt < KT; ++kt){
        mbar_wait(mb0 + 8*s, ph);
        const float* As = smf + s * STG_FL;
        const float* Bs = As + AFL;

        #pragma unroll
        for (int kk = 0; kk < BK; kk += 8){
            unsigned a[2][4];
            #pragma unroll
            for (int am = 0; am < 2; ++am){
                const int r = wm*32 + am*16 + g;
                a[am][0] = __float_as_uint(As[(r    )*(BK+APAD) + kk + tg    ]);
                a[am][1] = __float_as_uint(As[(r + 8)*(BK+APAD) + kk + tg    ]);
                a[am][2] = __float_as_uint(As[(r    )*(BK+APAD) + kk + tg + 4]);
                a[am][3] = __float_as_uint(As[(r + 8)*(BK+APAD) + kk + tg + 4]);
            }
            #pragma unroll
            for (int bn = 0; bn < 8; ++bn){
                unsigned b[2];
                const int cc = wn*64 + bn*8 + g;
                b[0] = __float_as_uint(Bs[(kk + tg    )*(BN+BPAD) + cc]);
                b[1] = __float_as_uint(Bs[(kk + tg + 4)*(BN+BPAD) + cc]);
                mma8(c[0][bn], a[0], b);
                mma8(c[1][bn], a[1], b);
            }
        }
        __syncthreads();
        if (tid == 0 && kt + NSTAGE < KT){
            mbar_expect(mb0 + 8*s, STG_BYTES);
            bulk_g2s(sb + s*STG_BYTES,         Asrc + ((size_t)tile*KT + kt + NSTAGE)*AFL, AFL*4, mb0 + 8*s);
            bulk_g2s(sb + s*STG_BYTES + AFL*4, Bw + (((size_t)e*KT + kt + NSTAGE)*NT + nt)*BFL, BFL*4, mb0 + 8*s);
        }
        if (++s == NSTAGE){ s = 0; ph ^= 1; }
    }

    // ---- epilogue ----
    #pragma unroll
    for (int am = 0; am < 2; ++am){
        #pragma unroll
        for (int bn = 0; bn < 8; ++bn){
            const int lc = wn*64 + bn*8 + 2*tg;
            const int gc = nt*BN + lc;                 // global output column
            const float bb0 = bias[e*(NT*BN) + gc];
            const float bb1 = bias[e*(NT*BN) + gc + 1];
            #pragma unroll
            for (int h = 0; h < 2; ++h){
                const int r = wm*32 + am*16 + g + h*8;
                float v0 = c[am][bn][h*2+0] + bb0;
                float v1 = c[am][bn][h*2+1] + bb1;
                if (FIRST){
                    v0 = __uint_as_float(f2tf(gelu_f(v0)));
                    v1 = __uint_as_float(f2tf(gelu_f(v1)));
                    float* dst = g_H + ((size_t)tile*(HH/BK) + (gc >> 5))*AFL
                               + r*(BK+APAD) + (gc & 31);
                    *(float2*)dst = make_float2(v0, v1);
                } else {
                    float* dst = g_Y + ((size_t)(tile*BM + r))*DD + gc;
                    *(float2*)dst = make_float2(v0, v1);
                }
            }
        }
    }
}

// ---------------- kernel 9: weighted combine (no atomics) -------------------
__global__ void combine_kernel(float* __restrict__ out){
    const int t = blockIdx.x, i = threadIdx.x;
    const int r0 = g_pos[2*t], r1 = g_pos[2*t+1];
    const float w0 = g_roww[r0], w1 = g_roww[r1];
    const float4 a = ((const float4*)(g_Y + (size_t)r0 * DD))[i];
    const float4 b = ((const float4*)(g_Y + (size_t)r1 * DD))[i];
    float4 r;
    r.x = w0*a.x + w1*b.x; r.y = w0*a.y + w1*b.y;
    r.z = w0*a.z + w1*b.z; r.w = w0*a.w + w1*b.w;
    ((float4*)(out + (size_t)t * DD))[i] = r;
}

// ---------------- launch -----------------------------------------------------
extern "C" void kernel_launch(void* const* d_in, const int* in_sizes, int n_in,
                              void* d_out, int out_size){
    // input order: x, top_k(scalar), Wg, bg, W1, b1, W2, b2 (robust to dropped scalar)
    const int sh = (n_in >= 8) ? 0 : -1;
    const float* x  = (const float*)d_in[0];
    const float* Wg = (const float*)d_in[2 + sh];
    const float* bg = (const float*)d_in[3 + sh];
    const float* W1 = (const float*)d_in[4 + sh];
    const float* b1 = (const float*)d_in[5 + sh];
    const float* W2 = (const float*)d_in[6 + sh];
    const float* b2 = (const float*)d_in[7 + sh];
    float* out = (float*)d_out;

    float* w1c; cudaGetSymbolAddress((void**)&w1c, g_W1c);
    float* w2c; cudaGetSymbolAddress((void**)&w2c, g_W2c);

    // opt into >48KB dynamic smem (host-side attribute set; not a stream op)
    cudaFuncSetAttribute(gemm_kernel<DD/BK, HH/BN, true >,
                         cudaFuncAttributeMaxDynamicSharedMemorySize, SMEM_BYTES);
    cudaFuncSetAttribute(gemm_kernel<HH/BK, DD/BN, false>,
                         cudaFuncAttributeMaxDynamicSharedMemorySize, SMEM_BYTES);

    init_kernel<<<1, 32>>>();
    gate_kernel<<<128, 256>>>(x, Wg, bg);
    scan_kernel<<<1, 32>>>();
    scatter_kernel<<<TT/256, 256>>>();
    padfill_kernel<<<EE, 128>>>();
    gather_kernel<<<PADROWS, 256>>>(x);
    convw_kernel<DD/BK, HH/BN><<<16384, 256>>>(W1, w1c);
    convw_kernel<HH/BK, DD/BN><<<16384, 256>>>(W2, w2c);
    gemm_kernel<DD/BK, HH/BN, true ><<<dim3(HH/BN, EE*64), 512, SMEM_BYTES>>>(w1c, b1);
    gemm_kernel<HH/BK, DD/BN, false><<<dim3(DD/BN, EE*64), 512, SMEM_BYTES>>>(w2c, b2);
    combine_kernel<<<TT, 256>>>(out);
}